// round 13
// baseline (speedup 1.0000x reference)
#include <cuda_runtime.h>
#include <cstdint>

// out[n,d] = mean_f( x[n,f]*W[f,d] + b[f,d] ) = (x@W)[n,d]/256 + mean_f b[f,d]
// N=8192, K=256, D=64. bf16 3-term split on tensor cores (mma.sync m16n8k16).
//
// transform kernel: x -> AfH/AfL (A-fragments in mma register layout, bf16
//   hi/lo), W -> Wf (B-fragments), b -> mb. Pure streaming.
// main kernel (PDL): NO smem, NO barriers. Per warp: 16 k-iters of
//   4x LDG.128 (L2-resident frags, 4-deep pipeline) + 6 independent HMMA.

typedef uint32_t u32;

#define NROWS  8192
#define NF     256
#define ND     64
#define TILE_M 16
#define NTILES (NROWS / TILE_M)        // 512
#define TTHREADS 256
#define TBLOCKS (NTILES + 16 + 1)      // 529
#define MTHREADS 128
#define MBLOCKS NTILES                 // 512

// A-frag tables: [tile][ki][lane] uint4  (512*16*32 entries)
__device__ uint4 AfH_g[NTILES * 16 * 32];
__device__ uint4 AfL_g[NTILES * 16 * 32];
// Wf[ki][col][t] : uint4 {hi(k=2t,2t+1), hi(k=2t+8,2t+9), lo(..), lo(..)}
__device__ uint4 Wf_g[16 * 64 * 4];
__device__ float mb_g[64];

__device__ __forceinline__ void cvt_split(float a, float b, u32& hi, u32& lo) {
    asm("cvt.rn.bf16x2.f32 %0, %1, %2;" : "=r"(hi) : "f"(b), "f"(a));
    float ha = __uint_as_float(hi << 16);
    float hb = __uint_as_float(hi & 0xFFFF0000u);
    float ra = a - ha;
    float rb = b - hb;
    asm("cvt.rn.bf16x2.f32 %0, %1, %2;" : "=r"(lo) : "f"(rb), "f"(ra));
}
__device__ __forceinline__ void mma16816(float* c, const uint4 a, u32 b0, u32 b1) {
    asm volatile(
        "mma.sync.aligned.m16n8k16.row.col.f32.bf16.bf16.f32 "
        "{%0,%1,%2,%3}, {%4,%5,%6,%7}, {%8,%9}, {%0,%1,%2,%3};"
        : "+f"(c[0]), "+f"(c[1]), "+f"(c[2]), "+f"(c[3])
        : "r"(a.x), "r"(a.y), "r"(a.z), "r"(a.w), "r"(b0), "r"(b1));
}

// ---------------- transform kernel ----------------
__global__ void __launch_bounds__(TTHREADS)
transform_kernel(const float* __restrict__ x,
                 const float* __restrict__ W,
                 const float* __restrict__ b)
{
    const int tid = threadIdx.x;
    const int bid = blockIdx.x;

    if (bid < NTILES) {
        // build A-fragments for tile bid: 512 entries, 2 per thread
        const int R = bid * TILE_M;
        #pragma unroll
        for (int e = 0; e < 2; ++e) {
            int idx  = e * TTHREADS + tid;     // 0..511
            int ki   = idx >> 5;
            int lane = idx & 31;
            int g    = lane >> 2;
            int t4   = lane & 3;
            int K    = ki * 16 + 2 * t4;
            const float* xr0 = x + (size_t)(R + g) * NF;
            const float* xr8 = x + (size_t)(R + 8 + g) * NF;
            float2 p0 = *(const float2*)(xr0 + K);       // a0: row g,   k,k+1
            float2 p1 = *(const float2*)(xr8 + K);       // a1: row g+8, k,k+1
            float2 p2 = *(const float2*)(xr0 + K + 8);   // a2: row g,   k+8,k+9
            float2 p3 = *(const float2*)(xr8 + K + 8);   // a3: row g+8, k+8,k+9
            u32 h0,l0,h1,l1,h2,l2,h3,l3;
            cvt_split(p0.x, p0.y, h0, l0);
            cvt_split(p1.x, p1.y, h1, l1);
            cvt_split(p2.x, p2.y, h2, l2);
            cvt_split(p3.x, p3.y, h3, l3);
            int o = (bid * 16 + ki) * 32 + lane;
            AfH_g[o] = make_uint4(h0, h1, h2, h3);
            AfL_g[o] = make_uint4(l0, l1, l2, l3);
        }
    } else if (bid < NTILES + 16) {
        // build Wf B-fragment table
        int idx = (bid - NTILES) * 256 + tid;      // 0..4095
        int ki  = idx >> 8;
        int col = (idx >> 2) & 63;
        int t   = idx & 3;
        int k0  = ki * 16 + 2 * t;
        float w0 = W[(k0    ) * ND + col];
        float w1 = W[(k0 + 1) * ND + col];
        float w2 = W[(k0 + 8) * ND + col];
        float w3 = W[(k0 + 9) * ND + col];
        u32 h01, l01, h23, l23;
        cvt_split(w0, w1, h01, l01);
        cvt_split(w2, w3, h23, l23);
        Wf_g[idx] = make_uint4(h01, h23, l01, l23);
    } else {
        // mb[d] = mean_f b[f][d]
        __shared__ float4 sc[256];
        const int qd = tid & 15;
        const int fr = tid >> 4;
        const float4* b4 = (const float4*)b;   // [256][16] float4
        float4 s = make_float4(0.f, 0.f, 0.f, 0.f);
        #pragma unroll
        for (int k = 0; k < 16; ++k) {
            float4 v = b4[(fr * 16 + k) * 16 + qd];
            s.x += v.x; s.y += v.y; s.z += v.z; s.w += v.w;
        }
        sc[tid] = s;
        __syncthreads();
        if (tid < 16) {
            float4 m = make_float4(0.f, 0.f, 0.f, 0.f);
            #pragma unroll
            for (int g = 0; g < 16; ++g) {
                float4 v = sc[tid + 16 * g];
                m.x += v.x; m.y += v.y; m.z += v.z; m.w += v.w;
            }
            const float inv = 1.f / 256.f;
            m.x *= inv; m.y *= inv; m.z *= inv; m.w *= inv;
            ((float4*)mb_g)[tid] = m;
        }
    }
    __threadfence();
    __syncthreads();
    asm volatile("griddepcontrol.launch_dependents;");
}

// ---------------- main kernel: no smem, no barriers ----------------
__global__ void __launch_bounds__(MTHREADS, 4)
nanembed_hmma_kernel(float* __restrict__ out)
{
    asm volatile("griddepcontrol.wait;");

    const int tid  = threadIdx.x;
    const int bid  = blockIdx.x;           // tile id
    const int wid  = tid >> 5;
    const int lane = tid & 31;
    const int n0   = wid * 16;
    const int g    = lane >> 2;
    const int t4   = lane & 3;

    const uint4* aH = AfH_g + (bid * 16) * 32 + lane;   // stride 32/ki
    const uint4* aL = AfL_g + (bid * 16) * 32 + lane;
    const uint4* bp0 = Wf_g + ((n0 + g) * 4 + t4);      // stride 256/ki
    const uint4* bp1 = bp0 + 32;

    float a0hh[4] = {0,0,0,0}, a0hl[4] = {0,0,0,0}, a0lh[4] = {0,0,0,0};
    float a1hh[4] = {0,0,0,0}, a1hl[4] = {0,0,0,0}, a1lh[4] = {0,0,0,0};

    // 4-deep prefetch pipeline
    uint4 AH[4], AL[4], B0[4], B1[4];
    #pragma unroll
    for (int p = 0; p < 4; ++p) {
        AH[p] = aH[p * 32];
        AL[p] = aL[p * 32];
        B0[p] = bp0[p * 256];
        B1[p] = bp1[p * 256];
    }

    #pragma unroll
    for (int ki = 0; ki < 16; ++ki) {
        const int s = ki & 3;
        uint4 ah = AH[s], al = AL[s], b0 = B0[s], b1 = B1[s];
        if (ki < 12) {
            AH[s] = aH[(ki + 4) * 32];
            AL[s] = aL[(ki + 4) * 32];
            B0[s] = bp0[(ki + 4) * 256];
            B1[s] = bp1[(ki + 4) * 256];
        }
        mma16816(a0hh, ah, b0.x, b0.y);   // hi*hi
        mma16816(a1hh, ah, b1.x, b1.y);
        mma16816(a0hl, ah, b0.z, b0.w);   // hi*lo
        mma16816(a1hl, ah, b1.z, b1.w);
        mma16816(a0lh, al, b0.x, b0.y);   // lo*hi
        mma16816(a1lh, al, b1.x, b1.y);
    }

    // ---- epilogue ----
    const float inv = 1.f / 256.f;
    const int grow = bid * TILE_M + g;
    {
        int col = n0 + 2 * t4;
        float2 m = *(const float2*)(mb_g + col);
        float s0 = a0hh[0] + a0hl[0] + a0lh[0];
        float s1 = a0hh[1] + a0hl[1] + a0lh[1];
        float s2 = a0hh[2] + a0hl[2] + a0lh[2];
        float s3 = a0hh[3] + a0hl[3] + a0lh[3];
        float2 o0, o1;
        o0.x = fmaf(s0, inv, m.x); o0.y = fmaf(s1, inv, m.y);
        o1.x = fmaf(s2, inv, m.x); o1.y = fmaf(s3, inv, m.y);
        *(float2*)(out + (size_t)grow * ND + col) = o0;
        *(float2*)(out + (size_t)(grow + 8) * ND + col) = o1;
    }
    {
        int col = n0 + 8 + 2 * t4;
        float2 m = *(const float2*)(mb_g + col);
        float s0 = a1hh[0] + a1hl[0] + a1lh[0];
        float s1 = a1hh[1] + a1hl[1] + a1lh[1];
        float s2 = a1hh[2] + a1hl[2] + a1lh[2];
        float s3 = a1hh[3] + a1hl[3] + a1lh[3];
        float2 o0, o1;
        o0.x = fmaf(s0, inv, m.x); o0.y = fmaf(s1, inv, m.y);
        o1.x = fmaf(s2, inv, m.x); o1.y = fmaf(s3, inv, m.y);
        *(float2*)(out + (size_t)grow * ND + col) = o0;
        *(float2*)(out + (size_t)(grow + 8) * ND + col) = o1;
    }
}

extern "C" void kernel_launch(void* const* d_in, const int* in_sizes, int n_in,
                              void* d_out, int out_size)
{
    const float* x = (const float*)d_in[0];
    const float* W = (const float*)d_in[1];
    const float* b = (const float*)d_in[2];
    float* out = (float*)d_out;

    transform_kernel<<<TBLOCKS, TTHREADS>>>(x, W, b);

    cudaLaunchConfig_t cfg = {};
    cfg.gridDim  = dim3(MBLOCKS, 1, 1);
    cfg.blockDim = dim3(MTHREADS, 1, 1);
    cfg.dynamicSmemBytes = 0;
    cudaLaunchAttribute attrs[1];
    attrs[0].id = cudaLaunchAttributeProgrammaticStreamSerialization;
    attrs[0].val.programmaticStreamSerializationAllowed = 1;
    cfg.attrs = attrs;
    cfg.numAttrs = 1;
    cudaLaunchKernelEx(&cfg, nanembed_hmma_kernel, out);
}